// round 7
// baseline (speedup 1.0000x reference)
#include <cuda_runtime.h>
#include <cstdint>

#define BATCH 128
#define TSTEPS 512
#define XD 256
#define RD 256
#define PH 512
#define MUD 2048
#define OD 256

__device__ float    g_phi[BATCH * PH];
__device__ float    g_r[BATCH * RD];
__device__ float    g_mu[BATCH * MUD];
__device__ unsigned g_bar[4];

// Stage a 32-row tile of `ncols` columns into shared "acts", transposed and
// XOR-swizzled:  acts[k*32 + (m ^ (k&31))] = gsrc[m*stride + (k - koff)].
template <bool CG>
__device__ __forceinline__ void stage32(float* acts, const float* gsrc,
                                        int stride, int ncols, int koff)
{
    const int t  = threadIdx.x;
    const int m  = t >> 2;        // 0..31
    const int cb = (t & 3) * 4;   // 0,4,8,12
    for (int c = cb; c < ncols; c += 16) {
        const float4* p = reinterpret_cast<const float4*>(gsrc + m * stride + c);
        float4 v = CG ? __ldcg(p) : __ldg(p);
        const int k = koff + c;
        acts[(k + 0) * 32 + (m ^ ((k + 0) & 31))] = v.x;
        acts[(k + 1) * 32 + (m ^ ((k + 1) & 31))] = v.y;
        acts[(k + 2) * 32 + (m ^ ((k + 2) & 31))] = v.z;
        acts[(k + 3) * 32 + (m ^ ((k + 3) & 31))] = v.w;
    }
}

// Ticket barrier across the 32 CTAs of one batch-group.
__device__ __forceinline__ void group_barrier(int mg, unsigned* tgt)
{
    __syncthreads();
    *tgt += 32u;
    if (threadIdx.x == 0) {
        __threadfence();
        atomicAdd(&g_bar[mg], 1u);
        const unsigned want = *tgt;
        while (*((volatile unsigned*)&g_bar[mg]) < want) { __nanosleep(40); }
        __threadfence();
    }
    __syncthreads();
}

__global__ void init_kernel(const float* __restrict__ b_mu2r)
{
    int i = blockIdx.x * blockDim.x + threadIdx.x;
    if (i < 4) g_bar[i] = 0u;
    if (i < BATCH * RD) {
        // r at step 0: relu(0 @ W^T + b) = relu(b)
        g_r[i] = fmaxf(b_mu2r[i & (RD - 1)], 0.0f);
    }
}

// Persistent SRU. Grid: 128 CTAs = 4 batch-groups (32 rows) x 32 slice-CTAs.
// Block: 128 threads. Dynamic shared: acts[512*32] + w1s[512*16] + w2s[512*32].
__global__ void __launch_bounds__(128, 1)
sru_persistent(const float* __restrict__ x,
               const float* __restrict__ Wmu2r,
               const float* __restrict__ bmu2r,
               const float* __restrict__ W1,
               const float* __restrict__ b1,
               const float* __restrict__ Wo,
               const float* __restrict__ bo,
               float* __restrict__ out)
{
    extern __shared__ float smem[];
    float* acts = smem;                        // 64 KB
    float* w1s  = smem + 512 * 32;             // 32 KB
    float* w2s  = smem + 512 * 32 + 512 * 16;  // 64 KB

    const int t     = threadIdx.x;
    const int cta   = blockIdx.x;
    const int mg    = cta >> 5;    // batch group 0..3
    const int sg    = cta & 31;    // slice group 0..31
    const int mbase = mg * 32;

    const int mIdx = t & 15;       // row-pair index
    const int gIdx = t >> 4;       // 0..7
    const int m0   = 2 * mIdx;

    // ---- stationary weight slices into shared (once per launch) ----
    for (int n = 0; n < 16; n++) {
        const float* src = W1 + (size_t)(sg * 16 + n) * 512;
        for (int k = t; k < 512; k += 128) w1s[k * 16 + n] = src[k];
    }
    for (int jj = 0; jj < 8; jj++) {
        for (int a = 0; a < 4; a++) {
            const float* src = Wmu2r + (size_t)(sg * 8 + jj) * MUD + a * 512;
            const int c = jj * 4 + a;
            for (int k = t; k < 512; k += 128) w2s[k * 32 + c] = src[k];
        }
    }

    const float alpha[4] = {0.0f, 0.5f, 0.9f, 0.99f};
    const float biasP0 = b1[sg * 16 + 2 * gIdx];
    const float biasP1 = b1[sg * 16 + 2 * gIdx + 1];
    const float bR     = bmu2r[sg * 8 + gIdx];

    float s_st[2][4];
    float mu_reg[16];
#pragma unroll
    for (int i = 0; i < 2; i++)
#pragma unroll
        for (int a = 0; a < 4; a++) s_st[i][a] = 0.0f;
#pragma unroll
    for (int i = 0; i < 16; i++) mu_reg[i] = 0.0f;

    unsigned bar_tgt = 0u;

    for (int step = 0; step < TSTEPS; step++) {
        // ---- stage Xcat = [x_t | r] ----
        stage32<false>(acts, x + (size_t)step * BATCH * XD + (size_t)mbase * XD,
                       XD, XD, 0);
        stage32<true>(acts, g_r + (size_t)mbase * RD, RD, RD, XD);
        __syncthreads();

        // ---- GEMM A: phi tile (32m x 16n), microtile 2m x 2n, K=512 ----
        float c00 = 0.f, c01 = 0.f, c10 = 0.f, c11 = 0.f;
        {
            const int n2 = 2 * gIdx;
#pragma unroll 32
            for (int k = 0; k < 512; k++) {
                const int base = (m0 ^ (k & 31)) & ~1;
                float2 ap = *reinterpret_cast<const float2*>(&acts[k * 32 + base]);
                const float a0 = (k & 1) ? ap.y : ap.x;
                const float a1 = (k & 1) ? ap.x : ap.y;
                float2 w = *reinterpret_cast<const float2*>(&w1s[k * 16 + n2]);
                c00 = fmaf(a0, w.x, c00);
                c01 = fmaf(a0, w.y, c01);
                c10 = fmaf(a1, w.x, c10);
                c11 = fmaf(a1, w.y, c11);
            }
        }
        {
            const int p0 = sg * 16 + 2 * gIdx;
            __stcg(&g_phi[(size_t)(mbase + m0) * PH + p0],         fmaxf(c00 + biasP0, 0.f));
            __stcg(&g_phi[(size_t)(mbase + m0) * PH + p0 + 1],     fmaxf(c01 + biasP1, 0.f));
            __stcg(&g_phi[(size_t)(mbase + m0 + 1) * PH + p0],     fmaxf(c10 + biasP0, 0.f));
            __stcg(&g_phi[(size_t)(mbase + m0 + 1) * PH + p0 + 1], fmaxf(c11 + biasP1, 0.f));
        }
        group_barrier(mg, &bar_tgt);

        // ---- stage phi ----
        stage32<true>(acts, g_phi + (size_t)mbase * PH, PH, PH, 0);
        __syncthreads();

        // ---- GEMM B: ps tile (32m x [8j x 4a]), microtile 2m x 4c, K=512 ----
        float acc[2][4];
#pragma unroll
        for (int i = 0; i < 2; i++)
#pragma unroll
            for (int a = 0; a < 4; a++) acc[i][a] = 0.0f;
        {
            const int c4 = 4 * gIdx;
#pragma unroll 32
            for (int k = 0; k < 512; k++) {
                const int base = (m0 ^ (k & 31)) & ~1;
                float2 ap = *reinterpret_cast<const float2*>(&acts[k * 32 + base]);
                const float a0 = (k & 1) ? ap.y : ap.x;
                const float a1 = (k & 1) ? ap.x : ap.y;
                float4 w = *reinterpret_cast<const float4*>(&w2s[k * 32 + c4]);
                acc[0][0] = fmaf(a0, w.x, acc[0][0]);
                acc[0][1] = fmaf(a0, w.y, acc[0][1]);
                acc[0][2] = fmaf(a0, w.z, acc[0][2]);
                acc[0][3] = fmaf(a0, w.w, acc[0][3]);
                acc[1][0] = fmaf(a1, w.x, acc[1][0]);
                acc[1][1] = fmaf(a1, w.y, acc[1][1]);
                acc[1][2] = fmaf(a1, w.z, acc[1][2]);
                acc[1][3] = fmaf(a1, w.w, acc[1][3]);
            }
        }

        // ---- s update (registers) + next-step r ----
#pragma unroll
        for (int mi = 0; mi < 2; mi++) {
            float ssum = 0.0f;
#pragma unroll
            for (int a = 0; a < 4; a++) {
                s_st[mi][a] = alpha[a] * s_st[mi][a] + (1.0f - alpha[a]) * acc[mi][a];
                ssum += s_st[mi][a];
            }
            const float rv = fmaxf(ssum + bR, 0.0f);
            __stcg(&g_r[(size_t)(mbase + m0 + mi) * RD + sg * 8 + gIdx], rv);
        }

        // ---- mu update (registers; phi from shared) ----
#pragma unroll
        for (int mi = 0; mi < 2; mi++) {
#pragma unroll
            for (int pi = 0; pi < 2; pi++) {
                const int p = sg * 16 + 2 * gIdx + pi;
                const float phv = acts[p * 32 + ((m0 + mi) ^ (p & 31))];
#pragma unroll
                for (int a = 0; a < 4; a++) {
                    const int idx = (mi * 2 + pi) * 4 + a;
                    mu_reg[idx] = alpha[a] * mu_reg[idx] + (1.0f - alpha[a]) * phv;
                }
            }
        }
        group_barrier(mg, &bar_tgt);
    }

    // ---- dump register mu ----
#pragma unroll
    for (int mi = 0; mi < 2; mi++) {
#pragma unroll
        for (int pi = 0; pi < 2; pi++) {
            const int p = sg * 16 + 2 * gIdx + pi;
#pragma unroll
            for (int a = 0; a < 4; a++) {
                const int idx = (mi * 2 + pi) * 4 + a;
                __stcg(&g_mu[(size_t)(mbase + m0 + mi) * MUD + a * 512 + p], mu_reg[idx]);
            }
        }
    }
    group_barrier(mg, &bar_tgt);

    // ---- final: out = relu(mu @ Wo^T + bo). Tile 32m x 8o, K=2048 in 4 chunks.
    float o0 = 0.0f, o1 = 0.0f;
    for (int ch = 0; ch < 4; ch++) {
        stage32<true>(acts, g_mu + (size_t)mbase * MUD + ch * 512, MUD, 512, 0);
        for (int n = 0; n < 8; n++) {
            const float* src = Wo + (size_t)(sg * 8 + n) * MUD + ch * 512;
            for (int k = t; k < 512; k += 128) w1s[k * 8 + n] = src[k];
        }
        __syncthreads();
#pragma unroll 16
        for (int k = 0; k < 512; k++) {
            const int base = (m0 ^ (k & 31)) & ~1;
            float2 ap = *reinterpret_cast<const float2*>(&acts[k * 32 + base]);
            const float a0 = (k & 1) ? ap.y : ap.x;
            const float a1 = (k & 1) ? ap.x : ap.y;
            const float w = w1s[k * 8 + gIdx];
            o0 = fmaf(a0, w, o0);
            o1 = fmaf(a1, w, o1);
        }
        __syncthreads();
    }
    {
        const int oc  = sg * 8 + gIdx;
        const float bov = bo[oc];
        out[(size_t)(mbase + m0) * OD + oc]     = fmaxf(o0 + bov, 0.0f);
        out[(size_t)(mbase + m0 + 1) * OD + oc] = fmaxf(o1 + bov, 0.0f);
    }
}

extern "C" void kernel_launch(void* const* d_in, const int* in_sizes, int n_in,
                              void* d_out, int out_size)
{
    const float* x     = (const float*)d_in[0];
    const float* Wmu2r = (const float*)d_in[1];
    const float* bmu2r = (const float*)d_in[2];
    const float* W1    = (const float*)d_in[3];
    const float* b1    = (const float*)d_in[4];
    const float* Wo    = (const float*)d_in[5];
    const float* bo    = (const float*)d_in[6];
    float* out = (float*)d_out;

    const int smem_bytes = (512 * 32 + 512 * 16 + 512 * 32) * sizeof(float); // 160 KB
    cudaFuncSetAttribute(sru_persistent,
                         cudaFuncAttributeMaxDynamicSharedMemorySize, smem_bytes);

    init_kernel<<<64, 512>>>(bmu2r);
    sru_persistent<<<128, 128, smem_bytes>>>(x, Wmu2r, bmu2r, W1, b1, Wo, bo, out);
}

// round 8
// speedup vs baseline: 1.2806x; 1.2806x over previous
#include <cuda_runtime.h>
#include <cstdint>
#include <cstring>

#define BATCH 128
#define TSTEPS 512
#define XD 256
#define RD 256
#define PH 512
#define MUD 2048
#define OD 256

typedef unsigned long long u64;

// packed f32x2 ops (sm_100+)
#define FMA2(c,a,b) asm("fma.rn.f32x2 %0, %1, %2, %0;" : "+l"(c) : "l"(a), "l"(b))
#define ADD2(c,a)   asm("add.rn.f32x2 %0, %1, %0;" : "+l"(c) : "l"(a))

__device__ __forceinline__ float2 u2f(u64 v) { float2 f; memcpy(&f, &v, 8); return f; }

__device__ float    g_phi[BATCH * PH];
__device__ float    g_r[BATCH * RD];
__device__ float    g_mu[BATCH * MUD];
__device__ unsigned g_bar[4];

// acts layout: value (m,k) lives at  m*512 + 2*((k>>1) ^ ((m>>1)&15)) + (k&1)
// -> k-pairs contiguous (8B aligned), XOR swizzle over k-pair index kills the
//    16-way bank conflict of the m-strided GEMM loads.
template <bool CG>
__device__ __forceinline__ void stage32p(float* acts, const float* gsrc,
                                         int stride, int ncols, int koff)
{
    const int t  = threadIdx.x;
    const int m  = t >> 3;           // 0..31
    const int mx = (m >> 1) & 15;
    const int cb = (t & 7) * 4;
    float* arow = acts + m * 512;
    const float* grow = gsrc + m * stride;
    for (int c = cb; c < ncols; c += 32) {
        const float4* p = reinterpret_cast<const float4*>(grow + c);
        float4 v = CG ? __ldcg(p) : __ldg(p);
        const int kp = (koff + c) >> 1;
        *reinterpret_cast<float2*>(arow + (((kp    ) ^ mx) << 1)) = make_float2(v.x, v.y);
        *reinterpret_cast<float2*>(arow + (((kp + 1) ^ mx) << 1)) = make_float2(v.z, v.w);
    }
}

// Ticket barrier across the 32 CTAs of one batch-group.
__device__ __forceinline__ void group_barrier(int mg, unsigned* tgt)
{
    __syncthreads();
    *tgt += 32u;
    if (threadIdx.x == 0) {
        __threadfence();
        atomicAdd(&g_bar[mg], 1u);
        const unsigned want = *tgt;
        while (*((volatile unsigned*)&g_bar[mg]) < want) { __nanosleep(40); }
        __threadfence();
    }
    __syncthreads();
}

__global__ void init_kernel(const float* __restrict__ b_mu2r)
{
    int i = blockIdx.x * blockDim.x + threadIdx.x;
    if (i < 4) g_bar[i] = 0u;
    if (i < BATCH * RD) {
        g_r[i] = fmaxf(b_mu2r[i & (RD - 1)], 0.0f);   // r0 = relu(b) since mu0 = 0
    }
}

// Persistent SRU. 128 CTAs = 4 batch-groups (32 rows) x 32 slice-CTAs.
// 256 threads = 2 K-halves x 128 workers. Weights stationary in smem.
__global__ void __launch_bounds__(256, 1)
sru_persistent(const float* __restrict__ x,
               const float* __restrict__ Wmu2r,
               const float* __restrict__ bmu2r,
               const float* __restrict__ W1,
               const float* __restrict__ b1,
               const float* __restrict__ Wo,
               const float* __restrict__ bo,
               float* __restrict__ out)
{
    extern __shared__ float smem[];
    float* acts = smem;                       // 16384 f (64 KB)
    float* w1s  = smem + 16384;               //  8192 f (32 KB)
    float* w2s  = smem + 24576;               // 16384 f (64 KB)
    u64*   red  = reinterpret_cast<u64*>(smem + 40960);   // 1024 u64 (8 KB)

    const int t     = threadIdx.x;
    const int ts    = t & 127;
    const int h     = t >> 7;        // K-half 0/1
    const int cta   = blockIdx.x;
    const int mg    = cta >> 5;
    const int sg    = cta & 31;
    const int mbase = mg * 32;

    const int mIdx = ts & 15;
    const int gIdx = ts >> 4;        // 0..7
    const int m0   = 2 * mIdx;
    const int mx   = mIdx;           // (m0>>1)&15 == ((m0+1)>>1)&15
    const int kp0  = h * 128;

    // ---- stationary weights into smem, k-pair interleaved layouts ----
    // w1s[(k>>1)*32 + n*2 + (k&1)] = W1[sg*16+n][k]          (n = 0..15)
    for (int n = 0; n < 16; n++) {
        const float* src = W1 + (size_t)(sg * 16 + n) * 512;
        for (int k = t; k < 512; k += 256)
            w1s[(k >> 1) * 32 + n * 2 + (k & 1)] = src[k];
    }
    // w2s[(k>>1)*64 + c*2 + (k&1)] = Wmu2r[sg*8+jj][a*512+k], c = jj*4+a
    for (int jj = 0; jj < 8; jj++)
        for (int a = 0; a < 4; a++) {
            const float* src = Wmu2r + (size_t)(sg * 8 + jj) * MUD + a * 512;
            const int c = jj * 4 + a;
            for (int k = t; k < 512; k += 256)
                w2s[(k >> 1) * 64 + c * 2 + (k & 1)] = src[k];
        }
    __syncthreads();

    const float alpha[4] = {0.0f, 0.5f, 0.9f, 0.99f};
    const float beta[4]  = {1.0f, 0.5f, 0.1f, 0.01f};
    const float biasP0 = b1[sg * 16 + 2 * gIdx];
    const float biasP1 = b1[sg * 16 + 2 * gIdx + 1];
    const float bR     = bmu2r[sg * 8 + gIdx];

    float s_st[2][4];                // only h==0 uses
    float mu_reg[8];                 // 2m x 2p x 2 alphas (this half's alphas)
#pragma unroll
    for (int i = 0; i < 2; i++)
#pragma unroll
        for (int a = 0; a < 4; a++) s_st[i][a] = 0.0f;
#pragma unroll
    for (int i = 0; i < 8; i++) mu_reg[i] = 0.0f;

    unsigned bar_tgt = 0u;

    for (int step = 0; step < TSTEPS; step++) {
        // ---- stage Xcat = [x_t | r] ----
        stage32p<false>(acts, x + (size_t)step * BATCH * XD + (size_t)mbase * XD,
                        XD, XD, 0);
        stage32p<true>(acts, g_r + (size_t)mbase * RD, RD, RD, XD);
        __syncthreads();

        // ---- GEMM A: 2m x 2n, f32x2 over k-pairs, this thread's K-half ----
        u64 cA[2][2] = {{0ull, 0ull}, {0ull, 0ull}};
        {
            const float* arow = acts + m0 * 512;
            const float* wA   = w1s + 4 * gIdx;
#pragma unroll 16
            for (int i = 0; i < 128; i++) {
                const int kp  = kp0 + i;
                const int off = (kp ^ mx) << 1;
                u64 a0 = *reinterpret_cast<const u64*>(arow + off);
                u64 a1 = *reinterpret_cast<const u64*>(arow + 512 + off);
                ulonglong2 w = *reinterpret_cast<const ulonglong2*>(wA + kp * 32);
                FMA2(cA[0][0], a0, w.x); FMA2(cA[0][1], a0, w.y);
                FMA2(cA[1][0], a1, w.x); FMA2(cA[1][1], a1, w.y);
            }
        }
        // ---- reduce K-halves, write phi ----
        if (h) {
            red[0 * 128 + ts] = cA[0][0]; red[1 * 128 + ts] = cA[0][1];
            red[2 * 128 + ts] = cA[1][0]; red[3 * 128 + ts] = cA[1][1];
        }
        __syncthreads();
        if (!h) {
            ADD2(cA[0][0], red[0 * 128 + ts]); ADD2(cA[0][1], red[1 * 128 + ts]);
            ADD2(cA[1][0], red[2 * 128 + ts]); ADD2(cA[1][1], red[3 * 128 + ts]);
            const int p0 = sg * 16 + 2 * gIdx;
            float2 f;
            f = u2f(cA[0][0]); __stcg(&g_phi[(mbase + m0)     * PH + p0],     fmaxf(f.x + f.y + biasP0, 0.f));
            f = u2f(cA[0][1]); __stcg(&g_phi[(mbase + m0)     * PH + p0 + 1], fmaxf(f.x + f.y + biasP1, 0.f));
            f = u2f(cA[1][0]); __stcg(&g_phi[(mbase + m0 + 1) * PH + p0],     fmaxf(f.x + f.y + biasP0, 0.f));
            f = u2f(cA[1][1]); __stcg(&g_phi[(mbase + m0 + 1) * PH + p0 + 1], fmaxf(f.x + f.y + biasP1, 0.f));
        }
        group_barrier(mg, &bar_tgt);

        // ---- stage phi ----
        stage32p<true>(acts, g_phi + (size_t)mbase * PH, PH, PH, 0);
        __syncthreads();

        // ---- GEMM B: 2m x 4c (c = j*4+a slice), f32x2 over k-pairs ----
        u64 accB[8] = {0ull,0ull,0ull,0ull,0ull,0ull,0ull,0ull};  // [mi*4+a]
        {
            const float* arow = acts + m0 * 512;
            const float* wB   = w2s + 8 * gIdx;
#pragma unroll 16
            for (int i = 0; i < 128; i++) {
                const int kp  = kp0 + i;
                const int off = (kp ^ mx) << 1;
                u64 a0 = *reinterpret_cast<const u64*>(arow + off);
                u64 a1 = *reinterpret_cast<const u64*>(arow + 512 + off);
                ulonglong2 w0 = *reinterpret_cast<const ulonglong2*>(wB + kp * 64);
                ulonglong2 w1 = *reinterpret_cast<const ulonglong2*>(wB + kp * 64 + 4);
                FMA2(accB[0], a0, w0.x); FMA2(accB[1], a0, w0.y);
                FMA2(accB[2], a0, w1.x); FMA2(accB[3], a0, w1.y);
                FMA2(accB[4], a1, w0.x); FMA2(accB[5], a1, w0.y);
                FMA2(accB[6], a1, w1.x); FMA2(accB[7], a1, w1.y);
            }
        }
        // ---- reduce, update s, write next r ----
        if (h) {
#pragma unroll
            for (int j = 0; j < 8; j++) red[j * 128 + ts] = accB[j];
        }
        __syncthreads();
        if (!h) {
#pragma unroll
            for (int j = 0; j < 8; j++) ADD2(accB[j], red[j * 128 + ts]);
#pragma unroll
            for (int mi = 0; mi < 2; mi++) {
                float ssum = 0.0f;
#pragma unroll
                for (int a = 0; a < 4; a++) {
                    float2 f = u2f(accB[mi * 4 + a]);
                    const float ps = f.x + f.y;
                    s_st[mi][a] = alpha[a] * s_st[mi][a] + beta[a] * ps;
                    ssum += s_st[mi][a];
                }
                __stcg(&g_r[(mbase + m0 + mi) * RD + sg * 8 + gIdx],
                       fmaxf(ssum + bR, 0.0f));
            }
        }
        // ---- mu update (both halves; this half's 2 alphas) ----
#pragma unroll
        for (int mi = 0; mi < 2; mi++) {
#pragma unroll
            for (int pi = 0; pi < 2; pi++) {
                const int p = sg * 16 + 2 * gIdx + pi;
                const float phv =
                    acts[(m0 + mi) * 512 + (((p >> 1) ^ mx) << 1) + (p & 1)];
#pragma unroll
                for (int ai = 0; ai < 2; ai++) {
                    const int a = 2 * h + ai;
                    const int idx = (mi * 2 + pi) * 2 + ai;
                    mu_reg[idx] = alpha[a] * mu_reg[idx] + beta[a] * phv;
                }
            }
        }
        group_barrier(mg, &bar_tgt);
    }

    // ---- dump register mu ----
#pragma unroll
    for (int mi = 0; mi < 2; mi++)
#pragma unroll
        for (int pi = 0; pi < 2; pi++) {
            const int p = sg * 16 + 2 * gIdx + pi;
#pragma unroll
            for (int ai = 0; ai < 2; ai++) {
                const int a = 2 * h + ai;
                __stcg(&g_mu[(size_t)(mbase + m0 + mi) * MUD + a * 512 + p],
                       mu_reg[(mi * 2 + pi) * 2 + ai]);
            }
        }
    group_barrier(mg, &bar_tgt);

    // ---- final: out = relu(mu @ Wo^T + bo); 32m x 8o, K = 2048 in 4 chunks
    u64 oP[2] = {0ull, 0ull};
    for (int ch = 0; ch < 4; ch++) {
        stage32p<true>(acts, g_mu + (size_t)mbase * MUD + ch * 512, MUD, 512, 0);
        for (int n = 0; n < 8; n++) {
            const float* src = Wo + (size_t)(sg * 8 + n) * MUD + ch * 512;
            for (int k = t; k < 512; k += 256)
                w1s[(k >> 1) * 16 + n * 2 + (k & 1)] = src[k];
        }
        __syncthreads();
        {
            const float* arow = acts + m0 * 512;
            const float* wO   = w1s + 2 * gIdx;
#pragma unroll 16
            for (int i = 0; i < 128; i++) {
                const int kp  = kp0 + i;
                const int off = (kp ^ mx) << 1;
                u64 a0 = *reinterpret_cast<const u64*>(arow + off);
                u64 a1 = *reinterpret_cast<const u64*>(arow + 512 + off);
                u64 w  = *reinterpret_cast<const u64*>(wO + kp * 16);
                FMA2(oP[0], a0, w);
                FMA2(oP[1], a1, w);
            }
        }
        __syncthreads();
    }
    if (h) { red[ts] = oP[0]; red[128 + ts] = oP[1]; }
    __syncthreads();
    if (!h) {
        ADD2(oP[0], red[ts]); ADD2(oP[1], red[128 + ts]);
        const int oc = sg * 8 + gIdx;
        const float bov = bo[oc];
        float2 f0 = u2f(oP[0]), f1 = u2f(oP[1]);
        out[(mbase + m0)     * OD + oc] = fmaxf(f0.x + f0.y + bov, 0.0f);
        out[(mbase + m0 + 1) * OD + oc] = fmaxf(f1.x + f1.y + bov, 0.0f);
    }
}

extern "C" void kernel_launch(void* const* d_in, const int* in_sizes, int n_in,
                              void* d_out, int out_size)
{
    const float* x     = (const float*)d_in[0];
    const float* Wmu2r = (const float*)d_in[1];
    const float* bmu2r = (const float*)d_in[2];
    const float* W1    = (const float*)d_in[3];
    const float* b1    = (const float*)d_in[4];
    const float* Wo    = (const float*)d_in[5];
    const float* bo    = (const float*)d_in[6];
    float* out = (float*)d_out;

    const int smem_bytes = 40960 * 4 + 1024 * 8;   // 172032 B
    cudaFuncSetAttribute(sru_persistent,
                         cudaFuncAttributeMaxDynamicSharedMemorySize, smem_bytes);

    init_kernel<<<64, 512>>>(bmu2r);
    sru_persistent<<<128, 256, smem_bytes>>>(x, Wmu2r, bmu2r, W1, b1, Wo, bo, out);
}